// round 1
// baseline (speedup 1.0000x reference)
#include <cuda_runtime.h>
#include <cuda_bf16.h>
#include <math.h>

// Problem constants
#define Bq   2
#define Tq   2048
#define Cq   1024
#define Hq   16
#define HSq  64
#define FFq  4096
#define BTq  (Bq*Tq)          // 4096
#define EPSq 1e-5f

// ---------------------------------------------------------------------------
// Scratch (device globals — allocation-free)
// ---------------------------------------------------------------------------
__device__ float g_h  [(size_t)BTq*Cq];               // ln1 output / reused as ln2 output
__device__ float g_q  [(size_t)Hq*BTq*HSq];           // [H][B*T][HS]
__device__ float g_k  [(size_t)Hq*BTq*HSq];
__device__ float g_v  [(size_t)Hq*BTq*HSq];
__device__ float g_S  [(size_t)Bq*Hq*Tq*Tq];          // scores / weights, [H*B][T][T] (z = h*B+b)
__device__ float g_att[(size_t)BTq*Cq];               // concat heads [B*T][H*HS]
__device__ float g_x1 [(size_t)BTq*Cq];               // residual 1
__device__ float g_ff [(size_t)BTq*FFq];              // FF hidden

// ---------------------------------------------------------------------------
// LayerNorm: one block per row, 256 threads, float4
// ---------------------------------------------------------------------------
__global__ __launch_bounds__(256)
void layernorm_kernel(const float* __restrict__ x, const float* __restrict__ w,
                      float* __restrict__ out)
{
    long long r = blockIdx.x;
    int t = threadIdx.x;
    const float4* xr = reinterpret_cast<const float4*>(x + r * Cq);
    float4 v = xr[t];
    float sum = v.x + v.y + v.z + v.w;
    float sq  = v.x*v.x + v.y*v.y + v.z*v.z + v.w*v.w;
    #pragma unroll
    for (int o = 16; o; o >>= 1) {
        sum += __shfl_xor_sync(0xffffffffu, sum, o);
        sq  += __shfl_xor_sync(0xffffffffu, sq,  o);
    }
    __shared__ float s1[8], s2[8];
    __shared__ float mu_s, rstd_s;
    int wid = t >> 5, lane = t & 31;
    if (lane == 0) { s1[wid] = sum; s2[wid] = sq; }
    __syncthreads();
    if (t == 0) {
        float S = 0.f, Q = 0.f;
        #pragma unroll
        for (int i = 0; i < 8; i++) { S += s1[i]; Q += s2[i]; }
        float mu  = S * (1.0f / Cq);
        float var = Q * (1.0f / Cq) - mu * mu;
        mu_s = mu;
        rstd_s = rsqrtf(var + EPSq);
    }
    __syncthreads();
    float mu = mu_s, rstd = rstd_s;
    float4 ww = reinterpret_cast<const float4*>(w)[t];
    float4 o;
    o.x = (v.x - mu) * rstd * ww.x;
    o.y = (v.y - mu) * rstd * ww.y;
    o.z = (v.z - mu) * rstd * ww.z;
    o.w = (v.w - mu) * rstd * ww.w;
    reinterpret_cast<float4*>(out + r * Cq)[t] = o;
}

// ---------------------------------------------------------------------------
// Generic batched tiled SGEMM.
// C[z] = A[z] * B[z] (+ bias) (+ res), row-major, grid.z split as z1 = z/Z2, z2 = z%Z2.
// CAUSAL_K: limit K to (blockIdx.y+1)*BM (lower-triangular A as attention weights).
// ---------------------------------------------------------------------------
template<int BM, int BN, int BK, int TM, int TN, bool BIAS, bool RELU, bool RES, bool CAUSAL_K>
__global__ __launch_bounds__(256)
void sgemm_kernel(const float* __restrict__ A, long long sA1, long long sA2,
                  const float* __restrict__ B, long long sB1, long long sB2,
                  const float* __restrict__ bias, long long sb1, long long sb2,
                  const float* __restrict__ res,  long long sr1, long long sr2,
                  float* __restrict__ C, long long sC1, long long sC2,
                  int Z2, int M, int N, int K, int lda, int ldb, int ldc)
{
    constexpr int NT = (BM/TM) * (BN/TN);
    static_assert(NT == 256, "256 threads");
    static_assert(BK % 4 == 0 && BN % 4 == 0, "vec4");

    int z  = blockIdx.z;
    int z1 = z / Z2, z2 = z % Z2;
    A += z1 * sA1 + z2 * sA2;
    B += z1 * sB1 + z2 * sB2;
    C += z1 * sC1 + z2 * sC2;
    const float* biasp = BIAS ? (bias + z1 * sb1 + z2 * sb2) : nullptr;
    const float* resp  = RES  ? (res  + z1 * sr1 + z2 * sr2) : nullptr;

    int m0 = blockIdx.y * BM;
    int n0 = blockIdx.x * BN;
    int Keff = CAUSAL_K ? min(K, m0 + BM) : K;

    __shared__ float As[BK][BM + 4];
    __shared__ float Bs[BK][BN];

    const int tid = threadIdx.x;
    const int tx = tid % (BN / TN);
    const int ty = tid / (BN / TN);

    float acc[TM][TN];
    #pragma unroll
    for (int i = 0; i < TM; i++)
        #pragma unroll
        for (int j = 0; j < TN; j++) acc[i][j] = 0.f;

    // A-loader mapping
    constexpr int A_TPR = BK / 4;          // threads per row (float4)
    constexpr int A_RPP = NT / A_TPR;      // rows per pass
    constexpr int A_PASSES = BM / A_RPP;
    const int a_kv  = tid % A_TPR;
    const int a_row = tid / A_TPR;
    // B-loader mapping
    constexpr int B_TPR = BN / 4;
    constexpr int B_RPP = NT / B_TPR;
    constexpr int B_PASSES = BK / B_RPP;
    const int b_nv = tid % B_TPR;
    const int b_kr = tid / B_TPR;

    for (int k0 = 0; k0 < Keff; k0 += BK) {
        #pragma unroll
        for (int p = 0; p < A_PASSES; p++) {
            int m = a_row + p * A_RPP;
            float4 v = *reinterpret_cast<const float4*>(
                A + (long long)(m0 + m) * lda + k0 + a_kv * 4);
            As[a_kv*4 + 0][m] = v.x;
            As[a_kv*4 + 1][m] = v.y;
            As[a_kv*4 + 2][m] = v.z;
            As[a_kv*4 + 3][m] = v.w;
        }
        #pragma unroll
        for (int p = 0; p < B_PASSES; p++) {
            int kk = b_kr + p * B_RPP;
            *reinterpret_cast<float4*>(&Bs[kk][b_nv * 4]) =
                *reinterpret_cast<const float4*>(
                    B + (long long)(k0 + kk) * ldb + n0 + b_nv * 4);
        }
        __syncthreads();

        #pragma unroll
        for (int kk = 0; kk < BK; kk++) {
            float af[TM], bf[TN];
            #pragma unroll
            for (int i = 0; i < TM; i++) af[i] = As[kk][ty * TM + i];
            #pragma unroll
            for (int j = 0; j < TN; j++) bf[j] = Bs[kk][tx * TN + j];
            #pragma unroll
            for (int i = 0; i < TM; i++)
                #pragma unroll
                for (int j = 0; j < TN; j++)
                    acc[i][j] += af[i] * bf[j];
        }
        __syncthreads();
    }

    #pragma unroll
    for (int i = 0; i < TM; i++) {
        int gm = m0 + ty * TM + i;
        #pragma unroll
        for (int j = 0; j < TN; j++) {
            int gn = n0 + tx * TN + j;
            float v = acc[i][j];
            if (BIAS) v += biasp[gn];
            if (RELU) v = fmaxf(v, 0.f);
            if (RES)  v += resp[(long long)gm * ldc + gn];
            C[(long long)gm * ldc + gn] = v;
        }
    }
}

// ---------------------------------------------------------------------------
// Scores: S[z][i][j] = (Q[z][i]·K[z][j]) * scale  for j<=i, -inf for j>i in the
// diagonal band; blocks fully above diagonal are skipped (never read later).
// z = h*B + b. Q/K layout [H][B*T][HS] => contiguous stride T*HS in z.
// ---------------------------------------------------------------------------
__global__ __launch_bounds__(256)
void scores_kernel(const float* __restrict__ q, const float* __restrict__ k,
                   float* __restrict__ S)
{
    constexpr int BM = 128, BN = 64, BK = 16, TM = 8, TN = 4;
    const int z  = blockIdx.z;
    const int m0 = blockIdx.y * BM;
    const int n0 = blockIdx.x * BN;
    if (n0 >= m0 + BM) return;   // entire tile above diagonal

    const float* Q  = q + (long long)z * Tq * HSq;
    const float* Km = k + (long long)z * Tq * HSq;
    float*       Sz = S + (long long)z * Tq * Tq;

    __shared__ float As[BK][BM + 4];
    __shared__ float Bs[BK][BN + 4];

    const int tid = threadIdx.x;
    const int tx = tid % (BN / TN);   // 16
    const int ty = tid / (BN / TN);   // 16

    float acc[TM][TN];
    #pragma unroll
    for (int i = 0; i < TM; i++)
        #pragma unroll
        for (int j = 0; j < TN; j++) acc[i][j] = 0.f;

    const int kv  = tid % 4;
    const int row = tid / 4;          // 0..63

    for (int k0 = 0; k0 < HSq; k0 += BK) {
        #pragma unroll
        for (int p = 0; p < 2; p++) {
            int m = row + p * 64;
            float4 v = *reinterpret_cast<const float4*>(
                Q + (long long)(m0 + m) * HSq + k0 + kv * 4);
            As[kv*4 + 0][m] = v.x;
            As[kv*4 + 1][m] = v.y;
            As[kv*4 + 2][m] = v.z;
            As[kv*4 + 3][m] = v.w;
        }
        {
            float4 v = *reinterpret_cast<const float4*>(
                Km + (long long)(n0 + row) * HSq + k0 + kv * 4);
            Bs[kv*4 + 0][row] = v.x;
            Bs[kv*4 + 1][row] = v.y;
            Bs[kv*4 + 2][row] = v.z;
            Bs[kv*4 + 3][row] = v.w;
        }
        __syncthreads();
        #pragma unroll
        for (int kk = 0; kk < BK; kk++) {
            float af[TM], bf[TN];
            #pragma unroll
            for (int i = 0; i < TM; i++) af[i] = As[kk][ty * TM + i];
            #pragma unroll
            for (int j = 0; j < TN; j++) bf[j] = Bs[kk][tx * TN + j];
            #pragma unroll
            for (int i = 0; i < TM; i++)
                #pragma unroll
                for (int j = 0; j < TN; j++)
                    acc[i][j] += af[i] * bf[j];
        }
        __syncthreads();
    }

    const float scale = 0.125f;  // HS^-0.5
    #pragma unroll
    for (int i = 0; i < TM; i++) {
        int gi = m0 + ty * TM + i;
        #pragma unroll
        for (int j = 0; j < TN; j++) {
            int gj = n0 + tx * TN + j;
            float v = acc[i][j] * scale;
            if (gj > gi) v = -INFINITY;
            Sz[(long long)gi * Tq + gj] = v;
        }
    }
}

// ---------------------------------------------------------------------------
// Column softmax (reference softmaxes over the QUERY axis i, not j!).
// One thread per column j: stats over i in [j, T), normalize i in
// [floor(j/128)*128, T) so the att GEMM (BM=128, causal-K) reads exact zeros.
// ---------------------------------------------------------------------------
__global__ __launch_bounds__(256)
void softmax_col_kernel(float* __restrict__ S)
{
    const int z = blockIdx.y;
    const int j = blockIdx.x * blockDim.x + threadIdx.x;
    float* Sz = S + (long long)z * Tq * Tq;

    float m = Sz[(long long)j * Tq + j];   // diagonal always finite
    float s = 1.0f;
    for (int i = j + 1; i < Tq; i++) {
        float v = Sz[(long long)i * Tq + j];
        if (v > m) { s = s * __expf(m - v) + 1.0f; m = v; }
        else       { s += __expf(v - m); }
    }
    float inv = 1.0f / s;
    int i0 = (j / 128) * 128;
    for (int i = i0; i < Tq; i++) {
        long long idx = (long long)i * Tq + j;
        float v = Sz[idx];
        Sz[idx] = __expf(v - m) * inv;   // -inf -> 0 above diagonal
    }
}

// ---------------------------------------------------------------------------
// Launch sequence
// ---------------------------------------------------------------------------
extern "C" void kernel_launch(void* const* d_in, const int* in_sizes, int n_in,
                              void* d_out, int out_size)
{
    const float* x     = (const float*)d_in[0];
    const float* ln1_w = (const float*)d_in[1];
    const float* Wq    = (const float*)d_in[2];
    const float* bq    = (const float*)d_in[3];
    const float* Wk    = (const float*)d_in[4];
    const float* bk    = (const float*)d_in[5];
    const float* Wv    = (const float*)d_in[6];
    const float* bv    = (const float*)d_in[7];
    const float* Wo    = (const float*)d_in[8];
    const float* bo    = (const float*)d_in[9];
    const float* ln2_w = (const float*)d_in[10];
    const float* W1    = (const float*)d_in[11];
    const float* b1    = (const float*)d_in[12];
    const float* W2    = (const float*)d_in[13];
    const float* b2    = (const float*)d_in[14];
    float* out = (float*)d_out;

    void *ph_, *pq_, *pk_, *pv_, *pS_, *patt_, *px1_, *pff_;
    cudaGetSymbolAddress(&ph_,  g_h);
    cudaGetSymbolAddress(&pq_,  g_q);
    cudaGetSymbolAddress(&pk_,  g_k);
    cudaGetSymbolAddress(&pv_,  g_v);
    cudaGetSymbolAddress(&pS_,  g_S);
    cudaGetSymbolAddress(&patt_, g_att);
    cudaGetSymbolAddress(&px1_, g_x1);
    cudaGetSymbolAddress(&pff_, g_ff);
    float* ph   = (float*)ph_;
    float* pq   = (float*)pq_;
    float* pk   = (float*)pk_;
    float* pv   = (float*)pv_;
    float* pS   = (float*)pS_;
    float* patt = (float*)patt_;
    float* px1  = (float*)px1_;
    float* pff  = (float*)pff_;

    // 1) LN1
    layernorm_kernel<<<BTq, 256>>>(x, ln1_w, ph);

    // 2) QKV projections: per-head GEMM [BT,1024] @ [1024,64] + bias, z = head
    {
        dim3 grid(1, BTq / 128, Hq);
        long long sW = (long long)Cq * HSq;     // per-head weight stride
        long long sC = (long long)BTq * HSq;    // per-head output stride
        sgemm_kernel<128,64,16,8,4,true,false,false,false><<<grid, 256>>>(
            ph, 0, 0, Wq, sW, 0, bq, HSq, 0, nullptr, 0, 0, pq, sC, 0,
            1, BTq, HSq, Cq, Cq, HSq, HSq);
        sgemm_kernel<128,64,16,8,4,true,false,false,false><<<grid, 256>>>(
            ph, 0, 0, Wk, sW, 0, bk, HSq, 0, nullptr, 0, 0, pk, sC, 0,
            1, BTq, HSq, Cq, Cq, HSq, HSq);
        sgemm_kernel<128,64,16,8,4,true,false,false,false><<<grid, 256>>>(
            ph, 0, 0, Wv, sW, 0, bv, HSq, 0, nullptr, 0, 0, pv, sC, 0,
            1, BTq, HSq, Cq, Cq, HSq, HSq);
    }

    // 3) Scores (causal, scaled), z = h*B+b
    {
        dim3 grid(Tq / 64, Tq / 128, Hq * Bq);
        scores_kernel<<<grid, 256>>>(pq, pk, pS);
    }

    // 4) Column softmax (query-axis)
    {
        dim3 grid(Tq / 256, Hq * Bq);
        softmax_col_kernel<<<grid, 256>>>(pS);
    }

    // 5) att = W @ V, causal-K; output scattered into [B*T][H*HS]
    {
        dim3 grid(1, Tq / 128, Hq * Bq);       // z1 = h, z2 = b (Z2 = B)
        sgemm_kernel<128,64,16,8,4,false,false,false,true><<<grid, 256>>>(
            pS, (long long)Bq * Tq * Tq, (long long)Tq * Tq,
            pv, (long long)Bq * Tq * HSq, (long long)Tq * HSq,
            nullptr, 0, 0, nullptr, 0, 0,
            patt, (long long)HSq, (long long)Tq * Cq,
            Bq, Tq, HSq, Tq, Tq, HSq, Cq);
    }

    // 6) x1 = x + att @ Wo + bo
    {
        dim3 grid(Cq / 128, BTq / 128, 1);
        sgemm_kernel<128,128,16,8,8,true,false,true,false><<<grid, 256>>>(
            patt, 0, 0, Wo, 0, 0, bo, 0, 0, x, 0, 0, px1, 0, 0,
            1, BTq, Cq, Cq, Cq, Cq, Cq);
    }

    // 7) LN2 (reuse g_h)
    layernorm_kernel<<<BTq, 256>>>(px1, ln2_w, ph);

    // 8) FF1: relu(h2 @ W1 + b1)
    {
        dim3 grid(FFq / 128, BTq / 128, 1);
        sgemm_kernel<128,128,16,8,8,true,true,false,false><<<grid, 256>>>(
            ph, 0, 0, W1, 0, 0, b1, 0, 0, nullptr, 0, 0, pff, 0, 0,
            1, BTq, FFq, Cq, Cq, FFq, FFq);
    }

    // 9) out = x1 + ff @ W2 + b2
    {
        dim3 grid(Cq / 128, BTq / 128, 1);
        sgemm_kernel<128,128,16,8,8,true,false,true,false><<<grid, 256>>>(
            pff, 0, 0, W2, 0, 0, b2, 0, 0, px1, 0, 0, out, 0, 0,
            1, BTq, Cq, FFq, FFq, Cq, Cq);
    }
}